// round 6
// baseline (speedup 1.0000x reference)
#include <cuda_runtime.h>
#include <cuda_bf16.h>
#include <math.h>

#define N_NODES 100000
#define N_EDGES 1600000
#define HID     128
#define NGRAPH  256

typedef unsigned long long ull;

// ---------------- scratch (device globals; no allocation anywhere) ---------
__device__ float g_A[(size_t)N_NODES * HID];      // h0 -> (layer2 agg) -> h2
__device__ float g_B[(size_t)N_NODES * HID];      // layer1 agg -> h1
__device__ float g_pooled[NGRAPH * HID];
__device__ float g_counts[NGRAPH];

// ---------------- helpers --------------------------------------------------
__device__ __forceinline__ void red_add_v4(float* addr, float4 v) {
    asm volatile("red.global.add.v4.f32 [%0], {%1,%2,%3,%4};"
                 :: "l"(__cvta_generic_to_global(addr)),
                    "f"(v.x), "f"(v.y), "f"(v.z), "f"(v.w)
                 : "memory");
}

// packed f32x2 FMA: d = a*b + c elementwise on (lo,hi) pairs
__device__ __forceinline__ ull ffma2(ull a, ull b, ull c) {
    ull d;
    asm("fma.rn.f32x2 %0, %1, %2, %3;" : "=l"(d) : "l"(a), "l"(b), "l"(c));
    return d;
}

// ---------------- 0a. zero a node-feature buffer ---------------------------
__global__ void zero_buf_kernel(int which)
{
    float4* p = (float4*)(which ? g_B : g_A);
    p[(size_t)blockIdx.x * 256 + threadIdx.x] = make_float4(0.f, 0.f, 0.f, 0.f);
}

// zero pooled sums + counts
__global__ void zero_pool_kernel()
{
    int idx = blockIdx.x * 256 + threadIdx.x;
    if (idx < NGRAPH * HID) g_pooled[idx] = 0.f;
    else                    g_counts[idx - NGRAPH * HID] = 0.f;
}

// ---------------- 1. embedding with max_norm=1 -----------------------------
__global__ void embed_kernel(const int* __restrict__ x,
                             const float* __restrict__ emb_w)
{
    int node = (blockIdx.x * 256 + threadIdx.x) >> 5;
    int lane = threadIdx.x & 31;
    int idx  = x[node];
    float4 v = *(const float4*)&emb_w[(size_t)idx * HID + lane * 4];
    float ss = v.x * v.x + v.y * v.y + v.z * v.z + v.w * v.w;
    #pragma unroll
    for (int o = 16; o > 0; o >>= 1)
        ss += __shfl_xor_sync(0xffffffffu, ss, o);
    float scale = fminf(1.0f, 1.0f / (sqrtf(ss) + 1e-7f));
    v.x *= scale; v.y *= scale; v.z *= scale; v.w *= scale;
    *(float4*)&g_A[(size_t)node * HID + lane * 4] = v;
}

// ---------------- 2. per-edge gather * w -> scatter-add --------------------
__global__ void __launch_bounds__(256)
edge_kernel(const int* __restrict__ ei,
            const float* __restrict__ ew,
            int layer)
{
    const float* h = layer ? g_B : g_A;
    float*     agg = layer ? g_A : g_B;
    int warp = (blockIdx.x * 256 + threadIdx.x) >> 5;
    int lane = threadIdx.x & 31;
    int e0 = warp * 2;
    int e1 = e0 + 1;

    int   src0 = ei[e0],           src1 = ei[e1];
    int   dst0 = ei[N_EDGES + e0], dst1 = ei[N_EDGES + e1];
    float w0   = ew[e0],           w1   = ew[e1];

    float4 v0 = *(const float4*)&h[(size_t)src0 * HID + lane * 4];
    float4 v1 = *(const float4*)&h[(size_t)src1 * HID + lane * 4];
    v0.x *= w0; v0.y *= w0; v0.z *= w0; v0.w *= w0;
    v1.x *= w1; v1.y *= w1; v1.z *= w1; v1.w *= w1;
    red_add_v4(&agg[(size_t)dst0 * HID + lane * 4], v0);
    red_add_v4(&agg[(size_t)dst1 * HID + lane * 4], v1);
}

// ---------------- 3. node update via packed f32x2 FMA ----------------------
// relu(agg@Wr^T + b + h@Wo^T). 64-node tiles, 256 threads.
// thread -> cols {jq, jq+32, jq+64, jq+96} x nodes ng*8..ng*8+7.
// Accumulators packed over K parity: acc = (sum even k, sum odd k).
// Weights used in ORIGINAL [j][k] layout -> (w[j][2q], w[j][2q+1]) is one ull.
// SMEM: features 64x128 f32 = 32KB + weight chunk 16x128 ull = 16KB = 48KB.
#define KCHUNK 16   // k-pairs per weight stage (16 pairs = 32 k)
__global__ void __launch_bounds__(256)
node_kernel(int layer, const float* __restrict__ w_rel,
            const float* __restrict__ w_root,
            const float* __restrict__ bias)
{
    __shared__ float sF[64 * 128];     // feature tile (agg, then h, then out)
    __shared__ ull   wS[KCHUNK * 128]; // weight chunk: [k-pair][j]

    const float* agg = layer ? g_A : g_B;
    const float* h   = layer ? g_B : g_A;
    float*       out = layer ? g_A : g_B;

    int tid = threadIdx.x;
    int jq  = tid & 31;
    int ng  = tid >> 5;
    size_t base = (size_t)blockIdx.x * 64;

    ull acc[8][4];
    #pragma unroll
    for (int n = 0; n < 8; n++)
        #pragma unroll
        for (int m = 0; m < 4; m++) acc[n][m] = 0ull;

    #pragma unroll
    for (int pass = 0; pass < 2; pass++) {
        const float* feat = pass ? h : agg;
        const ull*   w64  = (const ull*)(pass ? w_root : w_rel); // [j][64 k-pairs]

        // stage feature tile: 64 nodes x 32 float4
        __syncthreads();
        for (int i = tid; i < 64 * 32; i += 256) {
            int node = i >> 5, c4 = i & 31;
            size_t gn = base + node;
            if (gn >= N_NODES) gn = N_NODES - 1;      // clamp (masked on write)
            ((float4*)sF)[i] = *(const float4*)&feat[gn * HID + c4 * 4];
        }

        for (int chunk = 0; chunk < 64 / KCHUNK; chunk++) {
            __syncthreads();
            // stage weight chunk: wS[q][j] = w64[j*64 + chunk*KCHUNK + q]
            for (int i = tid; i < KCHUNK * 128; i += 256) {
                int j = i >> 4, q = i & (KCHUNK - 1);
                wS[q * 128 + j] = w64[(size_t)j * 64 + chunk * KCHUNK + q];
            }
            __syncthreads();

            #pragma unroll
            for (int q = 0; q < KCHUNK; q++) {
                ull w2[4];
                #pragma unroll
                for (int m = 0; m < 4; m++)
                    w2[m] = wS[q * 128 + jq + 32 * m];
                #pragma unroll
                for (int n = 0; n < 8; n++) {
                    ull a2 = *(const ull*)&sF[(ng * 8 + n) * 128 +
                                              chunk * (2 * KCHUNK) + 2 * q];
                    #pragma unroll
                    for (int m = 0; m < 4; m++)
                        acc[n][m] = ffma2(a2, w2[m], acc[n][m]);
                }
            }
        }
    }

    // fold parity halves + bias + relu, stage into sF[node][col]
    float b4[4];
    #pragma unroll
    for (int m = 0; m < 4; m++) b4[m] = __ldg(&bias[jq + 32 * m]);

    __syncthreads();
    #pragma unroll
    for (int n = 0; n < 8; n++) {
        int node = ng * 8 + n;
        #pragma unroll
        for (int m = 0; m < 4; m++) {
            unsigned int lo, hi;
            asm("mov.b64 {%0, %1}, %2;" : "=r"(lo), "=r"(hi) : "l"(acc[n][m]));
            float v = __uint_as_float(lo) + __uint_as_float(hi) + b4[m];
            sF[node * 128 + jq + 32 * m] = fmaxf(v, 0.f);
        }
    }
    __syncthreads();

    // coalesced float4 write-out
    for (int i = tid; i < 64 * 32; i += 256) {
        int node = i >> 5, c4 = i & 31;
        size_t gn = base + node;
        if (gn < N_NODES)
            *(float4*)&out[gn * HID + c4 * 4] = ((float4*)sF)[i];
    }
}

// ---------------- 4. mean pool (sums + counts) -----------------------------
__global__ void pool_kernel(const int* __restrict__ batch)
{
    int node = (blockIdx.x * 256 + threadIdx.x) >> 5;
    int lane = threadIdx.x & 31;
    int g = batch[node];
    float4 v = *(const float4*)&g_A[(size_t)node * HID + lane * 4];
    red_add_v4(&g_pooled[(size_t)g * HID + lane * 4], v);
    if (lane == 0) atomicAdd(&g_counts[g], 1.0f);
}

// ---------------- 5. classifier + softmax ----------------------------------
__global__ void cls_kernel(const float* __restrict__ w1,  // [64][128]
                           const float* __restrict__ b1,  // [64]
                           const float* __restrict__ w2,  // [2][64]
                           const float* __restrict__ b2,  // [2]
                           float* __restrict__ out)       // [256][2]
{
    int g = blockIdx.x;
    int j = threadIdx.x;                 // 0..63
    __shared__ float p[128];
    __shared__ float z[64];
    float inv = 1.0f / fmaxf(g_counts[g], 1.0f);
    p[j]      = g_pooled[g * HID + j] * inv;
    p[j + 64] = g_pooled[g * HID + j + 64] * inv;
    __syncthreads();
    float acc = b1[j];
    #pragma unroll 4
    for (int k = 0; k < 128; k++)
        acc += p[k] * w1[j * 128 + k];
    z[j] = fmaxf(acc, 0.f);
    __syncthreads();
    if (j == 0) {
        float l0 = b2[0], l1 = b2[1];
        #pragma unroll 4
        for (int k = 0; k < 64; k++) {
            l0 += z[k] * w2[k];
            l1 += z[k] * w2[64 + k];
        }
        float m  = fmaxf(l0, l1);
        float e0 = expf(l0 - m), e1 = expf(l1 - m);
        float s  = e0 + e1;
        out[g * 2]     = e0 / s;
        out[g * 2 + 1] = e1 / s;
    }
}

// ---------------- launch: KERNEL LAUNCHES ONLY ------------------------------
extern "C" void kernel_launch(void* const* d_in, const int* in_sizes, int n_in,
                              void* d_out, int out_size)
{
    const int*   x      = (const int*)  d_in[0];
    const int*   ei     = (const int*)  d_in[1];
    const float* ew     = (const float*)d_in[2];
    const int*   batch  = (const int*)  d_in[3];
    const float* emb_w  = (const float*)d_in[4];
    const float* w1_rel = (const float*)d_in[5];
    const float* b1_rel = (const float*)d_in[6];
    const float* w1_root= (const float*)d_in[7];
    const float* w2_rel = (const float*)d_in[8];
    const float* b2_rel = (const float*)d_in[9];
    const float* w2_root= (const float*)d_in[10];
    const float* cls1_w = (const float*)d_in[11];
    const float* cls1_b = (const float*)d_in[12];
    const float* cls2_w = (const float*)d_in[13];
    const float* cls2_b = (const float*)d_in[14];
    float* out = (float*)d_out;

    const int nodeTiles = (N_NODES + 63) / 64;   // 1563

    // embedding -> A
    embed_kernel<<<12500, 256>>>(x, emb_w);

    // layer 1: agg in B, h1 written in-place into B
    zero_buf_kernel<<<12500, 256>>>(1);
    edge_kernel<<<100000, 256>>>(ei, ew, 0);
    node_kernel<<<nodeTiles, 256>>>(0, w1_rel, w1_root, b1_rel);

    // layer 2: agg in A (h0 dead), h2 written in-place into A
    zero_buf_kernel<<<12500, 256>>>(0);
    edge_kernel<<<100000, 256>>>(ei, ew, 1);
    node_kernel<<<nodeTiles, 256>>>(1, w2_rel, w2_root, b2_rel);

    // pooling
    zero_pool_kernel<<<129, 256>>>();
    pool_kernel<<<12500, 256>>>(batch);

    // classifier + softmax
    cls_kernel<<<NGRAPH, 64>>>(cls1_w, cls1_b, cls2_w, cls2_b, out);
}